// round 4
// baseline (speedup 1.0000x reference)
#include <cuda_runtime.h>

// Problem constants (fixed shapes per reference)
#define NB      32
#define NC      64
#define NIN     10475
#define NOUT    2619
#define NNZ     (8 * NOUT)        // 20952
#define GPAIR   4                 // (b,c) pairs per block
#define NPAIR   (NB * NC)         // 2048
#define NBLK    (NPAIR / GPAIR)   // 512
#define THREADS 1024
#define MAXSLOT 32                // Poisson(8) per row; P(>=32) ~ 1e-11, guarded
#define SMEM_BYTES (NIN * GPAIR * sizeof(float))  // 167,600 B

// Device scratch (zero-initialized at module load; no runtime allocation)
__device__ int      d_cnt[NOUT];              // reset by last block each call
__device__ int2     d_entT[MAXSLOT * NOUT];   // slot-major {col, val} — coalesced
__device__ int      d_flag;                   // fill-complete flag
__device__ unsigned d_done;                   // block-completion ticket

// Single fused kernel:
//   block 0:  builds the transposed ELL table (overlaps with other blocks'
//             smem staging), then release-fences and sets d_flag.
//   all blocks: stage their 4 x-rows into smem as interleaved float4 granules,
//             spin on d_flag (usually already set), then compute 3 output
//             rows per thread in LOCKSTEP (3 independent load chains).
//   last block: resets d_cnt/d_flag/d_done for the next graph replay.
__global__ __launch_bounds__(THREADS, 1)
void k_main(const float* __restrict__ x,
            const int*   __restrict__ rows,
            const int*   __restrict__ cols,
            const float* __restrict__ vals,
            float*       __restrict__ out)
{
    extern __shared__ float4 sm4[];   // NIN granules: sm4[j] = {x[p0..p3][j]}
    const int tid = threadIdx.x;

    // ---- fill (block 0 only), overlapped with other blocks' staging ----
    if (blockIdx.x == 0) {
        for (int k = tid; k < NNZ; k += THREADS) {
            int r = rows[k];
            int slot = atomicAdd(&d_cnt[r], 1);
            if (slot < MAXSLOT)
                d_entT[slot * NOUT + r] = make_int2(cols[k], __float_as_int(vals[k]));
        }
        __syncthreads();
        __threadfence();                      // release entries + counts
        if (tid == 0) atomicExch(&d_flag, 1);
    }

    // ---- stage x rows into smem (4 coalesced streams -> STS.128) ----
    const int pb = blockIdx.x * GPAIR;
    const float* __restrict__ x0 = x + (size_t)pb * NIN;
    #pragma unroll 4
    for (int j = tid; j < NIN; j += THREADS) {
        sm4[j] = make_float4(__ldg(x0 + j),
                             __ldg(x0 + j + NIN),
                             __ldg(x0 + j + 2 * NIN),
                             __ldg(x0 + j + 3 * NIN));
    }

    // ---- wait for fill ----
    if (tid == 0) {
        while (*(volatile int*)&d_flag == 0) __nanosleep(64);
    }
    __syncthreads();       // staging done + flag observed for whole block
    __threadfence();       // acquire: order entry/count loads after flag

    // ---- compute: 3 rows per thread, interleaved k-loop (3 chains) ----
    const int r0 = tid;
    const int r1 = tid + THREADS;
    const int r2 = tid + 2 * THREADS;
    const bool h2 = (r2 < NOUT);

    int c0 = min(d_cnt[r0], MAXSLOT);
    int c1 = min(d_cnt[r1], MAXSLOT);
    int c2 = h2 ? min(d_cnt[r2], MAXSLOT) : 0;
    int cmax = max(c0, max(c1, c2));

    float4 a0 = make_float4(0.f, 0.f, 0.f, 0.f);
    float4 a1 = a0, a2 = a0;

    #pragma unroll 2
    for (int k = 0; k < cmax; k++) {
        const int2* __restrict__ ek = d_entT + k * NOUT;
        if (k < c0) {
            int2 e = __ldg(ek + r0);
            float v = __int_as_float(e.y);
            float4 xv = sm4[e.x];
            a0.x = fmaf(v, xv.x, a0.x); a0.y = fmaf(v, xv.y, a0.y);
            a0.z = fmaf(v, xv.z, a0.z); a0.w = fmaf(v, xv.w, a0.w);
        }
        if (k < c1) {
            int2 e = __ldg(ek + r1);
            float v = __int_as_float(e.y);
            float4 xv = sm4[e.x];
            a1.x = fmaf(v, xv.x, a1.x); a1.y = fmaf(v, xv.y, a1.y);
            a1.z = fmaf(v, xv.z, a1.z); a1.w = fmaf(v, xv.w, a1.w);
        }
        if (k < c2) {
            int2 e = __ldg(ek + r2);
            float v = __int_as_float(e.y);
            float4 xv = sm4[e.x];
            a2.x = fmaf(v, xv.x, a2.x); a2.y = fmaf(v, xv.y, a2.y);
            a2.z = fmaf(v, xv.z, a2.z); a2.w = fmaf(v, xv.w, a2.w);
        }
    }

    float* o0 = out + (size_t)pb * NOUT;
    o0[r0] = a0.x; o0[NOUT + r0] = a0.y; o0[2*NOUT + r0] = a0.z; o0[3*NOUT + r0] = a0.w;
    o0[r1] = a1.x; o0[NOUT + r1] = a1.y; o0[2*NOUT + r1] = a1.z; o0[3*NOUT + r1] = a1.w;
    if (h2) {
        o0[r2] = a2.x; o0[NOUT + r2] = a2.y; o0[2*NOUT + r2] = a2.z; o0[3*NOUT + r2] = a2.w;
    }

    // ---- last finished block resets scratch for the next replay ----
    __syncthreads();
    __shared__ unsigned s_last;
    if (tid == 0) {
        __threadfence();
        s_last = (atomicAdd(&d_done, 1u) == (unsigned)(gridDim.x - 1));
    }
    __syncthreads();
    if (s_last) {
        for (int i = tid; i < NOUT; i += THREADS) d_cnt[i] = 0;
        if (tid == 0) { d_flag = 0; d_done = 0; }
    }
}

// ---------------- launch ----------------

extern "C" void kernel_launch(void* const* d_in, const int* in_sizes, int n_in,
                              void* d_out, int out_size) {
    const float* x      = (const float*)d_in[0];
    const int*   M_rows = (const int*)d_in[1];
    const int*   M_cols = (const int*)d_in[2];
    const float* M_vals = (const float*)d_in[3];
    float* out = (float*)d_out;

    (void)in_sizes; (void)n_in; (void)out_size;

    cudaFuncSetAttribute(k_main, cudaFuncAttributeMaxDynamicSharedMemorySize,
                         (int)SMEM_BYTES);

    k_main<<<NBLK, THREADS, SMEM_BYTES>>>(x, M_rows, M_cols, M_vals, out);
}

// round 5
// speedup vs baseline: 1.3177x; 1.3177x over previous
#include <cuda_runtime.h>
#include <cstdint>

// Problem constants (fixed shapes per reference)
#define NB      32
#define NC      64
#define NIN     10475
#define NOUT    2619
#define NNZ     (8 * NOUT)        // 20952
#define GPAIR   2                 // (b,c) pairs per block
#define NPAIR   (NB * NC)         // 2048
#define NBLK    (NPAIR / GPAIR)   // 1024
#define THREADS 512
#define ROWS_PT 6                 // ceil(NOUT / THREADS)
#define MAXSLOT 32                // Poisson(8)/row; P(>=32) ~1e-11, guarded
#define SMEM_BYTES (NIN * GPAIR * sizeof(float))  // 83,800 B -> 2 CTAs/SM

// Device scratch (zero-init at load; no runtime allocation)
__device__ int            d_cnt[NOUT];              // reset by k_main's last block
__device__ unsigned short d_col16[MAXSLOT * NOUT];  // slot-major, coalesced
__device__ float          d_valT [MAXSLOT * NOUT];  // slot-major, coalesced
__device__ unsigned       d_done;

// ---------------- ELL fill (separate small launch; fusion regressed) -------
__global__ void k_fill(const int* __restrict__ rows,
                       const int* __restrict__ cols,
                       const float* __restrict__ vals) {
    int k = blockIdx.x * blockDim.x + threadIdx.x;
    if (k < NNZ) {
        int r = rows[k];
        int slot = atomicAdd(&d_cnt[r], 1);
        if (slot < MAXSLOT) {
            d_col16[slot * NOUT + r] = (unsigned short)cols[k];
            d_valT [slot * NOUT + r] = vals[k];
        }
    }
}

// ---------------- Main SpMM kernel ----------------
// GPAIR=2, 2 CTAs/SM: one CTA's L2-bound compute overlaps the other CTA's
// DRAM-bound staging. Staging via cp.async (no LDG->STS reg round-trip).
// Each thread owns 6 strided output rows, processed in lockstep (12
// independent entry loads per k-iteration).
__global__ __launch_bounds__(THREADS, 2)
void k_main(const float* __restrict__ x, float* __restrict__ out) {
    extern __shared__ float2 sm2[];   // NIN granules: sm2[j] = {x[p0][j], x[p1][j]}
    const int tid = threadIdx.x;
    const int pb = blockIdx.x * GPAIR;

    // ---- stage 2 x-rows into smem via cp.async 4B ----
    {
        uint32_t sbase = (uint32_t)__cvta_generic_to_shared(sm2);
        const float* __restrict__ x0 = x + (size_t)pb * NIN;
        const float* __restrict__ x1 = x0 + NIN;
        for (int j = tid; j < NIN; j += THREADS) {
            uint32_t dst = sbase + (uint32_t)j * 8u;
            asm volatile("cp.async.ca.shared.global [%0], [%1], 4;"
                         :: "r"(dst), "l"(x0 + j));
            asm volatile("cp.async.ca.shared.global [%0], [%1], 4;"
                         :: "r"(dst + 4u), "l"(x1 + j));
        }
        asm volatile("cp.async.commit_group;" ::: "memory");
        asm volatile("cp.async.wait_group 0;" ::: "memory");
    }
    __syncthreads();

    // ---- compute: 6 lockstep row-chains per thread ----
    int    c[ROWS_PT];
    float2 acc[ROWS_PT];
    int cmax = 0;
    #pragma unroll
    for (int i = 0; i < ROWS_PT; i++) {
        int r = tid + i * THREADS;
        c[i] = (r < NOUT) ? min(d_cnt[r], MAXSLOT) : 0;
        acc[i] = make_float2(0.f, 0.f);
        cmax = max(cmax, c[i]);
    }

    for (int k = 0; k < cmax; k++) {
        const unsigned short* __restrict__ ck = d_col16 + k * NOUT;
        const float*          __restrict__ vk = d_valT  + k * NOUT;
        #pragma unroll
        for (int i = 0; i < ROWS_PT; i++) {
            if (k < c[i]) {
                int r = tid + i * THREADS;
                int col = (int)__ldg(ck + r);
                float v = __ldg(vk + r);
                float2 xv = sm2[col];
                acc[i].x = fmaf(v, xv.x, acc[i].x);
                acc[i].y = fmaf(v, xv.y, acc[i].y);
            }
        }
    }

    float* __restrict__ o0 = out + (size_t)pb * NOUT;
    #pragma unroll
    for (int i = 0; i < ROWS_PT; i++) {
        int r = tid + i * THREADS;
        if (r < NOUT) {
            o0[r]        = acc[i].x;
            o0[NOUT + r] = acc[i].y;
        }
    }

    // ---- last finished block resets d_cnt for the next graph replay ----
    __syncthreads();
    __shared__ unsigned s_last;
    if (tid == 0) {
        __threadfence();
        s_last = (atomicAdd(&d_done, 1u) == (unsigned)(gridDim.x - 1));
    }
    __syncthreads();
    if (s_last) {
        for (int i = tid; i < NOUT; i += THREADS) d_cnt[i] = 0;
        if (tid == 0) d_done = 0;
    }
}

// ---------------- launch ----------------
extern "C" void kernel_launch(void* const* d_in, const int* in_sizes, int n_in,
                              void* d_out, int out_size) {
    const float* x      = (const float*)d_in[0];
    const int*   M_rows = (const int*)d_in[1];
    const int*   M_cols = (const int*)d_in[2];
    const float* M_vals = (const float*)d_in[3];
    float* out = (float*)d_out;

    (void)in_sizes; (void)n_in; (void)out_size;

    cudaFuncSetAttribute(k_main, cudaFuncAttributeMaxDynamicSharedMemorySize,
                         (int)SMEM_BYTES);

    k_fill<<<(NNZ + 255) / 256, 256>>>(M_rows, M_cols, M_vals);
    k_main<<<NBLK, THREADS, SMEM_BYTES>>>(x, out);
}

// round 6
// speedup vs baseline: 1.4031x; 1.0648x over previous
#include <cuda_runtime.h>
#include <cstdint>

// Problem constants (fixed shapes per reference)
#define NB      32
#define NC      64
#define NIN     10475
#define NOUT    2619
#define NNZ     (8 * NOUT)        // 20952
#define GPAIR   2                 // (b,c) pairs per block
#define NPAIR   (NB * NC)         // 2048
#define NBLK    (NPAIR / GPAIR)   // 1024
#define THREADS 512
#define ROWS_PT 6                 // ceil(NOUT / THREADS)
#define MAXSLOT 32                // Poisson(8)/row; P(>=32) ~1e-11, guarded
#define SM_STRIDE 10480           // floats per smem row; 4*10480 % 16 == 0, >= NIN+3 skew
#define SMEM_BYTES (GPAIR * SM_STRIDE * sizeof(float))  // 83,840 B -> 2 CTAs/SM

// Device scratch (zero-init at load; no runtime allocation)
__device__ int      d_cnt[NOUT];             // reset by k_main's last block
__device__ int2     d_entT[MAXSLOT * NOUT];  // slot-major {col, val-bits}, coalesced
__device__ unsigned d_done;

// ---------------- ELL fill ----------------
__global__ void k_fill(const int* __restrict__ rows,
                       const int* __restrict__ cols,
                       const float* __restrict__ vals) {
    int k = blockIdx.x * blockDim.x + threadIdx.x;
    if (k < NNZ) {
        int r = rows[k];
        int slot = atomicAdd(&d_cnt[r], 1);
        if (slot < MAXSLOT)
            d_entT[slot * NOUT + r] = make_int2(cols[k], __float_as_int(vals[k]));
    }
}

// Stage one x row into smem with 16B cp.async bulk + scalar head/tail.
// Row base in global isn't 16B-aligned, so the smem copy is placed at a
// per-row skew offset `off` such that element j lives at dstRow[off + j]
// and the 16B chunks are aligned on both sides. Returns `off`.
__device__ __forceinline__ int stage_row(const float* __restrict__ src,
                                         uint32_t dstRowAddr /*16B-aligned smem*/,
                                         int tid) {
    int m    = (int)((uintptr_t)src & 15u);      // 0,4,8,12
    int skew = ((16 - m) & 15) >> 2;             // floats until src is 16B-aligned
    int off  = (4 - skew) & 3;                   // dst element offset
    uint32_t dbase = dstRowAddr + (uint32_t)(off * 4);  // addr of element 0

    // head: j in [0, skew)
    for (int j = tid; j < skew; j += THREADS)
        asm volatile("cp.async.ca.shared.global [%0], [%1], 4;"
                     :: "r"(dbase + (uint32_t)(j * 4)), "l"(src + j));
    // bulk: 16B chunks starting at j = skew
    int nb4 = (NIN - skew) >> 2;
    for (int t = tid; t < nb4; t += THREADS) {
        int j = skew + t * 4;
        asm volatile("cp.async.cg.shared.global [%0], [%1], 16;"
                     :: "r"(dbase + (uint32_t)(j * 4)), "l"(src + j));
    }
    // tail
    int rem = (NIN - skew) & 3;
    int jt  = skew + nb4 * 4;
    for (int j = tid; j < rem; j += THREADS)
        asm volatile("cp.async.ca.shared.global [%0], [%1], 4;"
                     :: "r"(dbase + (uint32_t)((jt + j) * 4)), "l"(src + jt + j));
    return off;
}

// ---------------- Main SpMM kernel ----------------
// GPAIR=2, 2 CTAs/SM. Planar smem rows (with per-row skew), staged via 16B
// cp.async. Each thread owns 6 strided output rows in lockstep: per k-iter,
// 6 independent LDG.64 entry loads + 12 LDS.32 gathers.
__global__ __launch_bounds__(THREADS, 2)
void k_main(const float* __restrict__ x, float* __restrict__ out) {
    extern __shared__ float smf[];
    const int tid = threadIdx.x;
    const int pb  = blockIdx.x * GPAIR;

    uint32_t sbase = (uint32_t)__cvta_generic_to_shared(smf);
    const float* __restrict__ x0 = x + (size_t)pb * NIN;

    int offA = stage_row(x0,       sbase,                        tid);
    int offB = stage_row(x0 + NIN, sbase + SM_STRIDE * 4u,       tid) + SM_STRIDE;

    asm volatile("cp.async.commit_group;" ::: "memory");
    asm volatile("cp.async.wait_group 0;" ::: "memory");
    __syncthreads();

    // ---- compute: 6 lockstep row-chains per thread ----
    int    c[ROWS_PT];
    float2 acc[ROWS_PT];
    int cmax = 0;
    #pragma unroll
    for (int i = 0; i < ROWS_PT; i++) {
        int r = tid + i * THREADS;
        c[i] = (r < NOUT) ? min(d_cnt[r], MAXSLOT) : 0;
        acc[i] = make_float2(0.f, 0.f);
        cmax = max(cmax, c[i]);
    }

    for (int k = 0; k < cmax; k++) {
        const int2* __restrict__ ek = d_entT + k * NOUT;
        #pragma unroll
        for (int i = 0; i < ROWS_PT; i++) {
            if (k < c[i]) {
                int r = tid + i * THREADS;
                int2 e = __ldg(ek + r);
                float v  = __int_as_float(e.y);
                float xa = smf[offA + e.x];
                float xb = smf[offB + e.x];
                acc[i].x = fmaf(v, xa, acc[i].x);
                acc[i].y = fmaf(v, xb, acc[i].y);
            }
        }
    }

    float* __restrict__ o0 = out + (size_t)pb * NOUT;
    #pragma unroll
    for (int i = 0; i < ROWS_PT; i++) {
        int r = tid + i * THREADS;
        if (r < NOUT) {
            o0[r]        = acc[i].x;
            o0[NOUT + r] = acc[i].y;
        }
    }

    // ---- last finished block resets d_cnt for the next graph replay ----
    __syncthreads();
    __shared__ unsigned s_last;
    if (tid == 0) {
        __threadfence();
        s_last = (atomicAdd(&d_done, 1u) == (unsigned)(gridDim.x - 1));
    }
    __syncthreads();
    if (s_last) {
        for (int i = tid; i < NOUT; i += THREADS) d_cnt[i] = 0;
        if (tid == 0) d_done = 0;
    }
}

// ---------------- launch ----------------
extern "C" void kernel_launch(void* const* d_in, const int* in_sizes, int n_in,
                              void* d_out, int out_size) {
    const float* x      = (const float*)d_in[0];
    const int*   M_rows = (const int*)d_in[1];
    const int*   M_cols = (const int*)d_in[2];
    const float* M_vals = (const float*)d_in[3];
    float* out = (float*)d_out;

    (void)in_sizes; (void)n_in; (void)out_size;

    cudaFuncSetAttribute(k_main, cudaFuncAttributeMaxDynamicSharedMemorySize,
                         (int)SMEM_BYTES);

    k_fill<<<(NNZ + 255) / 256, 256>>>(M_rows, M_cols, M_vals);
    k_main<<<NBLK, THREADS, SMEM_BYTES>>>(x, out);
}

// round 7
// speedup vs baseline: 1.4496x; 1.0332x over previous
#include <cuda_runtime.h>
#include <cstdint>

// Problem constants (fixed shapes per reference)
#define NB      32
#define NC      64
#define NIN     10475
#define NOUT    2619
#define NNZ     (8 * NOUT)        // 20952
#define GPAIR   4                 // (b,c) pairs per block
#define NPAIR   (NB * NC)         // 2048
#define NBLK    (NPAIR / GPAIR)   // 512
#define THREADS 1024
#define ROWS_PT 3                 // ceil(NOUT / THREADS)
#define MAXSLOT 32                // Poisson(8)/row; P(>=32) ~1e-11, guarded
#define SMEM_BYTES (NIN * GPAIR * sizeof(float))  // 167,600 B -> 1 CTA/SM

// Device scratch (zero-init at load; no runtime allocation)
__device__ int      d_cnt[NOUT];             // reset by k_main's last block
__device__ int2     d_entT[MAXSLOT * NOUT];  // slot-major {col, val-bits}, coalesced
__device__ unsigned d_done;

// ---------------- ELL fill ----------------
__global__ void k_fill(const int* __restrict__ rows,
                       const int* __restrict__ cols,
                       const float* __restrict__ vals) {
    int k = blockIdx.x * blockDim.x + threadIdx.x;
    if (k < NNZ) {
        int r = rows[k];
        int slot = atomicAdd(&d_cnt[r], 1);
        if (slot < MAXSLOT)
            d_entT[slot * NOUT + r] = make_int2(cols[k], __float_as_int(vals[k]));
    }
}

// ---------------- Main SpMM kernel ----------------
// GPAIR=4: smem holds float4 granules sm4[j] = {x[p0..p3][j]} so one LDS.128
// per nnz entry serves 4 pairs (~1.75 L1 wavefronts/pair vs 3.4 for planar
// LDS.32). 1024 threads (32 warps, 1 CTA/SM). Each thread owns 3 strided
// output rows processed in lockstep: per k-iter, 3 independent LDG.64 entry
// loads + 3 LDS.128 gathers.
__global__ __launch_bounds__(THREADS, 1)
void k_main(const float* __restrict__ x, float* __restrict__ out) {
    extern __shared__ float4 sm4[];   // NIN granules
    const int tid = threadIdx.x;
    const int pb  = blockIdx.x * GPAIR;

    // ---- stage: 4 coalesced LDG.32 streams -> conflict-free STS.128 ----
    const float* __restrict__ x0 = x + (size_t)pb * NIN;
    #pragma unroll 4
    for (int j = tid; j < NIN; j += THREADS) {
        sm4[j] = make_float4(__ldg(x0 + j),
                             __ldg(x0 + j + NIN),
                             __ldg(x0 + j + 2 * NIN),
                             __ldg(x0 + j + 3 * NIN));
    }
    __syncthreads();

    // ---- compute: 3 lockstep row-chains per thread ----
    const int r0 = tid;
    const int r1 = tid + THREADS;
    const int r2 = tid + 2 * THREADS;
    const bool h2 = (r2 < NOUT);

    int c0 = min(d_cnt[r0], MAXSLOT);
    int c1 = min(d_cnt[r1], MAXSLOT);
    int c2 = h2 ? min(d_cnt[r2], MAXSLOT) : 0;
    const int cmax = max(c0, max(c1, c2));

    float4 a0 = make_float4(0.f, 0.f, 0.f, 0.f);
    float4 a1 = a0, a2 = a0;

    #pragma unroll 2
    for (int k = 0; k < cmax; k++) {
        const int2* __restrict__ ek = d_entT + k * NOUT;
        if (k < c0) {
            int2 e = __ldg(ek + r0);
            float v = __int_as_float(e.y);
            float4 xv = sm4[e.x];
            a0.x = fmaf(v, xv.x, a0.x); a0.y = fmaf(v, xv.y, a0.y);
            a0.z = fmaf(v, xv.z, a0.z); a0.w = fmaf(v, xv.w, a0.w);
        }
        if (k < c1) {
            int2 e = __ldg(ek + r1);
            float v = __int_as_float(e.y);
            float4 xv = sm4[e.x];
            a1.x = fmaf(v, xv.x, a1.x); a1.y = fmaf(v, xv.y, a1.y);
            a1.z = fmaf(v, xv.z, a1.z); a1.w = fmaf(v, xv.w, a1.w);
        }
        if (k < c2) {
            int2 e = __ldg(ek + r2);
            float v = __int_as_float(e.y);
            float4 xv = sm4[e.x];
            a2.x = fmaf(v, xv.x, a2.x); a2.y = fmaf(v, xv.y, a2.y);
            a2.z = fmaf(v, xv.z, a2.z); a2.w = fmaf(v, xv.w, a2.w);
        }
    }

    // ---- coalesced stores: 4 output streams ----
    float* __restrict__ o0 = out + (size_t)pb * NOUT;
    o0[r0] = a0.x; o0[NOUT + r0] = a0.y; o0[2*NOUT + r0] = a0.z; o0[3*NOUT + r0] = a0.w;
    o0[r1] = a1.x; o0[NOUT + r1] = a1.y; o0[2*NOUT + r1] = a1.z; o0[3*NOUT + r1] = a1.w;
    if (h2) {
        o0[r2] = a2.x; o0[NOUT + r2] = a2.y; o0[2*NOUT + r2] = a2.z; o0[3*NOUT + r2] = a2.w;
    }

    // ---- last finished block resets d_cnt for the next graph replay ----
    __syncthreads();
    __shared__ unsigned s_last;
    if (tid == 0) {
        __threadfence();
        s_last = (atomicAdd(&d_done, 1u) == (unsigned)(gridDim.x - 1));
    }
    __syncthreads();
    if (s_last) {
        for (int i = tid; i < NOUT; i += THREADS) d_cnt[i] = 0;
        if (tid == 0) d_done = 0;
    }
}

// ---------------- launch ----------------
extern "C" void kernel_launch(void* const* d_in, const int* in_sizes, int n_in,
                              void* d_out, int out_size) {
    const float* x      = (const float*)d_in[0];
    const int*   M_rows = (const int*)d_in[1];
    const int*   M_cols = (const int*)d_in[2];
    const float* M_vals = (const float*)d_in[3];
    float* out = (float*)d_out;

    (void)in_sizes; (void)n_in; (void)out_size;

    cudaFuncSetAttribute(k_main, cudaFuncAttributeMaxDynamicSharedMemorySize,
                         (int)SMEM_BYTES);

    k_fill<<<(NNZ + 255) / 256, 256>>>(M_rows, M_cols, M_vals);
    k_main<<<NBLK, THREADS, SMEM_BYTES>>>(x, out);
}

// round 8
// speedup vs baseline: 1.5767x; 1.0876x over previous
#include <cuda_runtime.h>
#include <cstdint>

// Problem constants (fixed shapes per reference)
#define NB      32
#define NC      64
#define NIN     10475
#define NOUT    2619
#define NNZ     (8 * NOUT)        // 20952
#define GPAIR   4                 // (b,c) pairs per block
#define NPAIR   (NB * NC)         // 2048
#define NBLK    (NPAIR / GPAIR)   // 512
#define THREADS 512
#define ROWS_PT 6                 // ceil(NOUT / THREADS)
#define MAXSLOT 32                // Poisson(4) per half-row; overflow ~impossible, guarded
#define HALF    5238              // column split point (ceil(NIN/2))
#define SMCOLS  5240              // padded float4 granules per half
#define SMEM_BYTES (SMCOLS * sizeof(float4))  // 83,840 B -> 2 CTAs/SM

// Device scratch (zero-init at load; no runtime allocation)
__device__ int      d_cntL[NOUT];             // per-half counts; reset each call
__device__ int      d_cntH[NOUT];
__device__ int2     d_entL[MAXSLOT * NOUT];   // slot-major {col_local, val-bits}
__device__ int2     d_entH[MAXSLOT * NOUT];
__device__ unsigned d_done;

// ---------------- ELL fill, bucketed by column half ----------------
__global__ void k_fill(const int* __restrict__ rows,
                       const int* __restrict__ cols,
                       const float* __restrict__ vals) {
    int k = blockIdx.x * blockDim.x + threadIdx.x;
    if (k < NNZ) {
        int r = rows[k];
        int c = cols[k];
        int vb = __float_as_int(vals[k]);
        if (c < HALF) {
            int slot = atomicAdd(&d_cntL[r], 1);
            if (slot < MAXSLOT) d_entL[slot * NOUT + r] = make_int2(c, vb);
        } else {
            int slot = atomicAdd(&d_cntH[r], 1);
            if (slot < MAXSLOT) d_entH[slot * NOUT + r] = make_int2(c - HALF, vb);
        }
    }
}

// ---------------- Main SpMM kernel ----------------
// Block owns 4 pairs; processes columns in TWO half-phases so smem fits
// 83.8 KB -> 2 CTAs/SM: one CTA's DRAM staging overlaps the other's compute.
// smem float4-interleaved: one LDS.128 per entry serves all 4 pairs.
// Accumulators persist across halves; output written once, coalesced.
__global__ __launch_bounds__(THREADS, 2)
void k_main(const float* __restrict__ x, float* __restrict__ out) {
    extern __shared__ float4 sm4[];   // SMCOLS granules
    const int tid = threadIdx.x;
    const int pb  = blockIdx.x * GPAIR;

    float4 acc[ROWS_PT];
    #pragma unroll
    for (int i = 0; i < ROWS_PT; i++) acc[i] = make_float4(0.f, 0.f, 0.f, 0.f);

    #pragma unroll
    for (int h = 0; h < 2; h++) {
        const int ncols = h ? (NIN - HALF) : HALF;
        const float* __restrict__ xh = x + (size_t)pb * NIN + h * HALF;

        // ---- stage this column half: 4 coalesced streams -> STS.128 ----
        for (int j = tid; j < ncols; j += THREADS) {
            sm4[j] = make_float4(__ldg(xh + j),
                                 __ldg(xh + j + NIN),
                                 __ldg(xh + j + 2 * NIN),
                                 __ldg(xh + j + 3 * NIN));
        }
        __syncthreads();

        // ---- accumulate this half's entries: 6 lockstep row-chains ----
        const int*  __restrict__ cnt = h ? d_cntH : d_cntL;
        const int2* __restrict__ tbl = h ? d_entH : d_entL;

        int c[ROWS_PT];
        int cmax = 0;
        #pragma unroll
        for (int i = 0; i < ROWS_PT; i++) {
            int r = tid + i * THREADS;
            c[i] = (r < NOUT) ? min(cnt[r], MAXSLOT) : 0;
            cmax = max(cmax, c[i]);
        }

        for (int k = 0; k < cmax; k++) {
            const int2* __restrict__ ek = tbl + k * NOUT;
            #pragma unroll
            for (int i = 0; i < ROWS_PT; i++) {
                if (k < c[i]) {
                    int2 e = __ldg(ek + tid + i * THREADS);
                    float v  = __int_as_float(e.y);
                    float4 xv = sm4[e.x];
                    acc[i].x = fmaf(v, xv.x, acc[i].x);
                    acc[i].y = fmaf(v, xv.y, acc[i].y);
                    acc[i].z = fmaf(v, xv.z, acc[i].z);
                    acc[i].w = fmaf(v, xv.w, acc[i].w);
                }
            }
        }
        __syncthreads();   // smem reused by next half
    }

    // ---- coalesced stores: 4 output streams x 6 rows ----
    float* __restrict__ o0 = out + (size_t)pb * NOUT;
    #pragma unroll
    for (int i = 0; i < ROWS_PT; i++) {
        int r = tid + i * THREADS;
        if (r < NOUT) {
            o0[r]            = acc[i].x;
            o0[NOUT + r]     = acc[i].y;
            o0[2 * NOUT + r] = acc[i].z;
            o0[3 * NOUT + r] = acc[i].w;
        }
    }

    // ---- last finished block resets counts for the next graph replay ----
    __shared__ unsigned s_last;
    if (tid == 0) {
        __threadfence();
        s_last = (atomicAdd(&d_done, 1u) == (unsigned)(gridDim.x - 1));
    }
    __syncthreads();
    if (s_last) {
        for (int i = tid; i < NOUT; i += THREADS) { d_cntL[i] = 0; d_cntH[i] = 0; }
        if (tid == 0) d_done = 0;
    }
}

// ---------------- launch ----------------
extern "C" void kernel_launch(void* const* d_in, const int* in_sizes, int n_in,
                              void* d_out, int out_size) {
    const float* x      = (const float*)d_in[0];
    const int*   M_rows = (const int*)d_in[1];
    const int*   M_cols = (const int*)d_in[2];
    const float* M_vals = (const float*)d_in[3];
    float* out = (float*)d_out;

    (void)in_sizes; (void)n_in; (void)out_size;

    cudaFuncSetAttribute(k_main, cudaFuncAttributeMaxDynamicSharedMemorySize,
                         (int)SMEM_BYTES);

    k_fill<<<(NNZ + 255) / 256, 256>>>(M_rows, M_cols, M_vals);
    k_main<<<NBLK, THREADS, SMEM_BYTES>>>(x, out);
}